// round 11
// baseline (speedup 1.0000x reference)
#include <cuda_runtime.h>
#include <cuda_fp16.h>
#include <cstdint>

// ---------------- problem constants ----------------
#define BATCH 1024
#define DIM   512
#define NCLS  100000

// ---------------- GEMM tiling ----------------
#define BM 128
#define BN 128
#define BK 64                            // fp16: 64 k per chunk
#define NCHUNKS (DIM / BK)               // 8
#define NBT (BATCH / BM)                 // 8 b-tiles
#define NCT ((NCLS + BN - 1) / BN)       // 782 c-tiles
#define NTILES (NBT * NCT)               // 6256
#define STAGES 4
#define A_BYTES (BM * BK * 2)            // 16384
#define B_BYTES (BN * BK * 2)            // 16384
#define STAGE_BYTES (A_BYTES + B_BYTES)  // 32768
#define DYN_SMEM (STAGES * STAGE_BYTES)  // 131072
#define NTHREADS 512

#define NWCHUNK ((NCLS + 1023) / 1024)   // 98 weight progress chunks (1024 rows)

// scratch (static device arrays — no allocation). Referenced ONLY in device code
// (host-side use of a __device__ symbol yields the shadow address — R7 bug).
__device__ __half g_xh[BATCH * DIM];            // normalized input, fp16-rn
__device__ __half g_wh[(size_t)NCLS * DIM];     // normalized weight, fp16-rn (102 MB)
// progress flags: rows completed. Monotonic across graph replays (>= checks);
// replay rewrites of g_xh/g_wh are bit-identical, so late readers are safe.
__device__ int g_acnt;                          // input rows done (>= BATCH)
__device__ int g_wcnt[NWCHUNK];                 // weight rows done per 1024-row chunk

// ---------------- helpers ----------------
__device__ __forceinline__ uint32_t smem_u32(const void* p) {
    uint32_t a;
    asm("{ .reg .u64 t; cvta.to.shared.u64 t, %1; cvt.u32.u64 %0, t; }" : "=r"(a) : "l"(p));
    return a;
}
__device__ __forceinline__ void cp16(uint32_t saddr, const void* g, bool valid) {
    int sz = valid ? 16 : 0;
    asm volatile("cp.async.cg.shared.global.L2::128B [%0], [%1], 16, %2;\n"
                 :: "r"(saddr), "l"(g), "r"(sz) : "memory");
}
__device__ __forceinline__ void ldsm_x4(uint32_t* r, uint32_t addr) {
    asm volatile("ldmatrix.sync.aligned.m8n8.x4.shared.b16 {%0,%1,%2,%3}, [%4];"
                 : "=r"(r[0]), "=r"(r[1]), "=r"(r[2]), "=r"(r[3]) : "r"(addr));
}
// m16n8k16 fp16 MMA, fp16 accumulate
__device__ __forceinline__ void mma_f16acc(uint32_t* d, const uint32_t* a, uint32_t b0, uint32_t b1) {
    asm volatile(
        "mma.sync.aligned.m16n8k16.row.col.f16.f16.f16.f16 "
        "{%0,%1}, {%2,%3,%4,%5}, {%6,%7}, {%0,%1};\n"
        : "+r"(d[0]), "+r"(d[1])
        : "r"(a[0]), "r"(a[1]), "r"(a[2]), "r"(a[3]), "r"(b0), "r"(b1));
}
__device__ __forceinline__ int ld_flag(const int* p) {
    int v;
    asm volatile("ld.global.cv.s32 %0, [%1];" : "=r"(v) : "l"(p));
    return v;
}

// ---------------- producer: normalize all rows -> fp16 + progress flags ----------------
// Warp-per-row grid-stride (input rows first, then weight rows); no block
// barriers — each warp independently publishes its row. 152 blocks x 8 warps
// = 1216 rows in flight; finishes in ~60-75us, far ahead of GEMM consumption.
__global__ void __launch_bounds__(256) k_norm_all(
    const float* __restrict__ input, const float* __restrict__ weight)
{
    if (threadIdx.x == 0) cudaTriggerProgrammaticLaunchCompletion();
    const int lane = threadIdx.x & 31;
    const int gw = blockIdx.x * 8 + (threadIdx.x >> 5);
    const int stride = gridDim.x * 8;
    for (int row = gw; row < BATCH + NCLS; row += stride) {
        const bool isA = row < BATCH;
        const int r = isA ? row : row - BATCH;
        const float* src = (isA ? input : weight) + (size_t)r * DIM;
        float4 v[4];
        #pragma unroll
        for (int i = 0; i < 4; i++) v[i] = *(const float4*)(src + lane * 4 + i * 128);
        float ss = 0.0f;
        #pragma unroll
        for (int i = 0; i < 4; i++)
            ss += v[i].x * v[i].x + v[i].y * v[i].y + v[i].z * v[i].z + v[i].w * v[i].w;
        #pragma unroll
        for (int o = 16; o; o >>= 1) ss += __shfl_xor_sync(0xffffffffu, ss, o);
        float inv = 1.0f / fmaxf(sqrtf(ss), 1e-12f);
        __half* drow = (isA ? g_xh : g_wh) + (size_t)r * DIM;
        #pragma unroll
        for (int i = 0; i < 4; i++) {
            __half2 h0 = __floats2half2_rn(v[i].x * inv, v[i].y * inv);
            __half2 h1 = __floats2half2_rn(v[i].z * inv, v[i].w * inv);
            uint2 pk;
            pk.x = *(uint32_t*)&h0;
            pk.y = *(uint32_t*)&h1;
            *(uint2*)(drow + lane * 4 + i * 128) = pk;
        }
        __threadfence();   // every lane: its own stores visible at gpu scope
        __syncwarp();      // all lanes' fences done before the flag bump
        if (lane == 0) atomicAdd(isA ? &g_acnt : &g_wcnt[r >> 10], 1);
    }
}

// ---------------- ArcFace epilogue math ----------------
__device__ __forceinline__ float arcface(float cosv, bool tgt) {
    if (!tgt) return 30.0f * cosv;
    float s2 = fminf(fmaxf(1.0f - cosv * cosv, 0.0f), 1.0f);
    float sine = sqrtf(s2);
    float phi = cosv * 0.8775825618903728f - sine * 0.479425538604203f;
    phi = (cosv > -0.8775825618903728f) ? phi : (cosv - 7.191383079063045f);
    return 30.0f * phi;
}

// Called by thread 0 only. One weight chunk per tile (1024 % 128 == 0).
__device__ __forceinline__ void wait_tile_t0(int cb) {
    while (ld_flag(&g_acnt) < BATCH) __nanosleep(128);
    const int c = cb >> 10;
    const int tgt = (c == NWCHUNK - 1) ? (NCLS - (NWCHUNK - 1) * 1024) : 1024;
    while (ld_flag(&g_wcnt[c]) < tgt) __nanosleep(128);
}

// ---------------- persistent pipelined fp16 GEMM + fused ArcFace ----------------
// grid = #SMs; each CTA walks tiles t = p, p+G, ... with the cp.async pipeline
// flowing continuously across tile boundaries. Readiness: thread 0 polls once
// per tile, released to the block by the existing per-chunk __syncthreads.
__global__ void __launch_bounds__(NTHREADS, 1) k_gemm(
    const int* __restrict__ label,
    float* __restrict__ out)
{
    extern __shared__ __align__(128) char dyn[];

    const int tid = threadIdx.x;
    const int lane = tid & 31;
    const int wid = tid >> 5;
    const uint32_t sbase = smem_u32(dyn);
    const int p = blockIdx.x;
    const int G = gridDim.x;

    if (p >= NTILES) return;
    const int myTiles = (NTILES - 1 - p) / G + 1;
    const int FMAX = myTiles * NCHUNKS;

    // warp grid 4(b) x 4(c): each warp computes 32 x 32
    const int warp_b = (wid & 3) * 32;
    const int warp_c = (wid >> 2) * 32;
    const int gid = lane >> 2;
    const int tig = lane & 3;

    // fp16 ldmatrix.x4 lane mapping: row-in-16 = lane&15, 16B k-chunk = lane>>4
    const int frow = lane & 15;
    const int fcq = lane >> 4;

    float acc[2][4][4];
    #pragma unroll
    for (int i = 0; i < 2; i++)
        #pragma unroll
        for (int j = 0; j < 4; j++)
            #pragma unroll
            for (int k = 0; k < 4; k++) acc[i][j][k] = 0.0f;

    // ---- flattened-chunk loader: f -> (tile, chunk) ----
    auto load_f = [&](int f) {
        const int t = p + (f >> 3) * G;
        const int k0 = (f & 7) * BK;
        const int bb = (t & (NBT - 1)) * BM;
        const int cb = (t >> 3) * BN;
        const uint32_t ab = sbase + (f & (STAGES - 1)) * STAGE_BYTES;
        #pragma unroll
        for (int l = 0; l < 2; l++) {           // A: 1024 ops
            int op = tid + l * NTHREADS;
            int r = op >> 3, q = op & 7;        // q: 16B chunk = 8 fp16
            uint32_t sa = ab + r * 128 + ((q ^ (r & 7)) << 4);
            cp16(sa, g_xh + (bb + r) * DIM + k0 + q * 8, true);
        }
        #pragma unroll
        for (int l = 0; l < 2; l++) {           // B: 1024 ops
            int op = tid + l * NTHREADS;
            int r = op >> 3, q = op & 7;
            int cc = cb + r;
            uint32_t sa = ab + A_BYTES + r * 128 + ((q ^ (r & 7)) << 4);
            cp16(sa, g_wh + (size_t)cc * DIM + k0 + q * 8, cc < NCLS);
        }
    };

    // prologue: wait for this CTA's first tile, then fill 3 stages
    if (tid == 0) wait_tile_t0((p >> 3) * BN);
    __syncthreads();
    for (int f = 0; f < 3; f++) {
        if (f < FMAX) load_f(f);
        asm volatile("cp.async.commit_group;" ::: "memory");
    }

    // fp16 accumulators live across 2 chunks (128 k), then flush to f32
    uint32_t hacc[2][4][2];

    for (int f = 0; f < FMAX; f++) {
        asm volatile("cp.async.wait_group 2;" ::: "memory");
        // thread 0: readiness poll for the tile the upcoming load targets
        // (only when f+3 starts a new tile); barrier below releases the block.
        if (tid == 0 && ((f + 3) & 7) == 0 && f + 3 < FMAX)
            wait_tile_t0((((p + ((f + 3) >> 3) * G)) >> 3) * BN);
        __syncthreads();   // also orders prior-iteration smem reads before overwrite

        if (f + 3 < FMAX) load_f(f + 3);
        asm volatile("cp.async.commit_group;" ::: "memory");

        const uint32_t a_stage = sbase + (f & (STAGES - 1)) * STAGE_BYTES;
        const uint32_t b_stage = a_stage + A_BYTES;
        const int chunk = f & 7;

        if ((chunk & 1) == 0) {
            #pragma unroll
            for (int i = 0; i < 2; i++)
                #pragma unroll
                for (int j = 0; j < 4; j++) { hacc[i][j][0] = 0u; hacc[i][j][1] = 0u; }
        }

        #pragma unroll
        for (int s = 0; s < 4; s++) {           // 4 x k16 steps per 64-chunk
            const int q = 2 * s + fcq;          // 16B chunk within row
            uint32_t bf[2][4];
            #pragma unroll
            for (int pp = 0; pp < 2; pp++) {
                int r = warp_c + pp * 16 + frow;
                uint32_t addr = b_stage + r * 128 + (((q ^ (r & 7)) & 7) << 4);
                ldsm_x4(bf[pp], addr);
            }
            #pragma unroll
            for (int mt = 0; mt < 2; mt++) {
                int r = warp_b + mt * 16 + frow;
                uint32_t addr = a_stage + r * 128 + (((q ^ (r & 7)) & 7) << 4);
                uint32_t af[4];
                ldsm_x4(af, addr);
                #pragma unroll
                for (int nt = 0; nt < 4; nt++)
                    mma_f16acc(hacc[mt][nt], af, bf[nt >> 1][nt & 1], bf[nt >> 1][(nt & 1) + 2]);
            }
        }

        if (chunk & 1) {
            // flush fp16 accs (128 k worth) into fp32 accumulators
            #pragma unroll
            for (int mt = 0; mt < 2; mt++)
                #pragma unroll
                for (int nt = 0; nt < 4; nt++) {
                    float2 f0 = __half22float2(*(__half2*)&hacc[mt][nt][0]);
                    float2 f1 = __half22float2(*(__half2*)&hacc[mt][nt][1]);
                    acc[mt][nt][0] += f0.x;
                    acc[mt][nt][1] += f0.y;
                    acc[mt][nt][2] += f1.x;
                    acc[mt][nt][3] += f1.y;
                }
        }

        if (chunk == 7) {
            // ---- fused ArcFace epilogue for finished tile (regs+gmem only) ----
            const int t = p + (f >> 3) * G;
            const int bb = (t & (NBT - 1)) * BM;
            const int cb = (t >> 3) * BN;
            #pragma unroll
            for (int mt = 0; mt < 2; mt++) {
                int r = warp_b + mt * 16 + gid;
                int glb0 = bb + r;
                int glb1 = glb0 + 8;
                int lab0 = label[glb0];
                int lab1 = label[glb1];
                #pragma unroll
                for (int nt = 0; nt < 4; nt++) {
                    int c = cb + warp_c + nt * 8 + 2 * tig;
                    if (c >= NCLS) continue;  // c even, NCLS even -> c+1 valid when c < NCLS
                    float2 o0, o1;
                    o0.x = arcface(acc[mt][nt][0], lab0 == c);
                    o0.y = arcface(acc[mt][nt][1], lab0 == c + 1);
                    o1.x = arcface(acc[mt][nt][2], lab1 == c);
                    o1.y = arcface(acc[mt][nt][3], lab1 == c + 1);
                    *(float2*)(out + (size_t)glb0 * NCLS + c) = o0;
                    *(float2*)(out + (size_t)glb1 * NCLS + c) = o1;
                    acc[mt][nt][0] = 0.0f; acc[mt][nt][1] = 0.0f;
                    acc[mt][nt][2] = 0.0f; acc[mt][nt][3] = 0.0f;
                }
            }
        }
    }
}

extern "C" void kernel_launch(void* const* d_in, const int* in_sizes, int n_in,
                              void* d_out, int out_size) {
    const float* input  = (const float*)d_in[0];
    const int*   label  = (const int*)d_in[1];
    const float* weight = (const float*)d_in[2];
    float* out = (float*)d_out;

    cudaFuncSetAttribute(k_gemm, cudaFuncAttributeMaxDynamicSharedMemorySize, DYN_SMEM);

    int nsm = 148;
    cudaDeviceGetAttribute(&nsm, cudaDevAttrMultiProcessorCount, 0);

    // producer: one 256-thread block per SM (co-resides with the GEMM CTA)
    k_norm_all<<<nsm, 256>>>(input, weight);

    // GEMM as PDL secondary: may start while k_norm_all runs; data dependencies
    // enforced by the thread0-per-tile flag polls.
    cudaLaunchConfig_t cfg = {};
    cfg.gridDim = dim3(nsm, 1, 1);
    cfg.blockDim = dim3(NTHREADS, 1, 1);
    cfg.dynamicSmemBytes = DYN_SMEM;
    cfg.stream = 0;
    cudaLaunchAttribute at[1];
    at[0].id = cudaLaunchAttributeProgrammaticStreamSerialization;
    at[0].val.programmaticStreamSerializationAllowed = 1;
    cfg.attrs = at;
    cfg.numAttrs = 1;
    cudaError_t e = cudaLaunchKernelEx(&cfg, k_gemm, label, out);
    if (e != cudaSuccess) {
        cudaGetLastError();   // clear sticky error, fall back to serial launch
        k_gemm<<<nsm, NTHREADS, DYN_SMEM>>>(label, out);
    }
}

// round 12
// speedup vs baseline: 1.8831x; 1.8831x over previous
#include <cuda_runtime.h>
#include <cuda_fp16.h>
#include <cstdint>

// ---------------- problem constants ----------------
#define BATCH 1024
#define DIM   512
#define NCLS  100000

// ---------------- GEMM tiling ----------------
#define BM 128
#define BN 128
#define BK 128                           // fp16: 128 k per chunk (256B smem rows)
#define NCHUNKS (DIM / BK)               // 4
#define NBT (BATCH / BM)                 // 8 b-tiles
#define NCT ((NCLS + BN - 1) / BN)       // 782 c-tiles
#define NTILES (NBT * NCT)               // 6256
#define STAGES 3
#define A_BYTES (BM * BK * 2)            // 32768
#define B_BYTES (BN * BK * 2)            // 32768
#define STAGE_BYTES (A_BYTES + B_BYTES)  // 65536
#define DYN_SMEM (STAGES * STAGE_BYTES)  // 196608
#define NTHREADS 512

// scratch (static device arrays — no allocation). Referenced ONLY in device code
// (host-side use of a __device__ symbol yields the shadow address — R7 bug).
__device__ __half g_xh[BATCH * DIM];            // normalized input, fp16-rn
__device__ __half g_wh[(size_t)NCLS * DIM];     // normalized weight, fp16-rn (102 MB)

// ---------------- helpers ----------------
__device__ __forceinline__ uint32_t smem_u32(const void* p) {
    uint32_t a;
    asm("{ .reg .u64 t; cvta.to.shared.u64 t, %1; cvt.u32.u64 %0, t; }" : "=r"(a) : "l"(p));
    return a;
}
__device__ __forceinline__ void cp16(uint32_t saddr, const void* g, bool valid) {
    int sz = valid ? 16 : 0;
    asm volatile("cp.async.cg.shared.global.L2::128B [%0], [%1], 16, %2;\n"
                 :: "r"(saddr), "l"(g), "r"(sz) : "memory");
}
__device__ __forceinline__ void ldsm_x4(uint32_t* r, uint32_t addr) {
    asm volatile("ldmatrix.sync.aligned.m8n8.x4.shared.b16 {%0,%1,%2,%3}, [%4];"
                 : "=r"(r[0]), "=r"(r[1]), "=r"(r[2]), "=r"(r[3]) : "r"(addr));
}
// m16n8k16 fp16 MMA, fp16 accumulate
__device__ __forceinline__ void mma_f16acc(uint32_t* d, const uint32_t* a, uint32_t b0, uint32_t b1) {
    asm volatile(
        "mma.sync.aligned.m16n8k16.row.col.f16.f16.f16.f16 "
        "{%0,%1}, {%2,%3,%4,%5}, {%6,%7}, {%0,%1};\n"
        : "+r"(d[0]), "+r"(d[1])
        : "r"(a[0]), "r"(a[1]), "r"(a[2]), "r"(a[3]), "r"(b0), "r"(b1));
}

// ---------------- fused row-normalize -> fp16 (warp per row, MLP=4) ----------------
template <int NROWS, int DSTSEL>
__global__ void k_rownorm(const float* __restrict__ src) {
    int warp = (blockIdx.x * blockDim.x + threadIdx.x) >> 5;
    int lane = threadIdx.x & 31;
    if (warp >= NROWS) return;
    const float* row = src + (size_t)warp * DIM;
    float4 v[4];
    #pragma unroll
    for (int i = 0; i < 4; i++) v[i] = *(const float4*)(row + lane * 4 + i * 128);
    float ss = 0.0f;
    #pragma unroll
    for (int i = 0; i < 4; i++)
        ss += v[i].x * v[i].x + v[i].y * v[i].y + v[i].z * v[i].z + v[i].w * v[i].w;
    #pragma unroll
    for (int o = 16; o; o >>= 1) ss += __shfl_xor_sync(0xffffffffu, ss, o);
    float inv = 1.0f / fmaxf(sqrtf(ss), 1e-12f);
    __half* dst = (DSTSEL == 0) ? g_xh : g_wh;   // device-side symbol resolution
    __half* drow = dst + (size_t)warp * DIM;
    #pragma unroll
    for (int i = 0; i < 4; i++) {
        __half2 h0 = __floats2half2_rn(v[i].x * inv, v[i].y * inv);
        __half2 h1 = __floats2half2_rn(v[i].z * inv, v[i].w * inv);
        uint2 pk;
        pk.x = *(uint32_t*)&h0;
        pk.y = *(uint32_t*)&h1;
        *(uint2*)(drow + lane * 4 + i * 128) = pk;
    }
}

// ---------------- ArcFace epilogue math ----------------
__device__ __forceinline__ float arcface(float cosv, bool tgt) {
    if (!tgt) return 30.0f * cosv;
    float s2 = fminf(fmaxf(1.0f - cosv * cosv, 0.0f), 1.0f);
    float sine = sqrtf(s2);
    float phi = cosv * 0.8775825618903728f - sine * 0.479425538604203f;
    phi = (cosv > -0.8775825618903728f) ? phi : (cosv - 7.191383079063045f);
    return 30.0f * phi;
}

// ---------------- persistent pipelined fp16 GEMM + fused ArcFace ----------------
// grid = #SMs; each CTA walks tiles t = p, p+G, ... with the cp.async pipeline
// flowing continuously across tile boundaries. BK=128 (256B smem rows, 64KB
// stages, 3 stages): half the barrier iterations of the BK=64 version.
// Swizzle: 16B chunk q of row r lives at r*256 + ((q ^ (r&7)) << 4) — conflict-
// free for cp.async stores and ldmatrix reads (perm mod 8 spans all 8 values).
__global__ void __launch_bounds__(NTHREADS, 1) k_gemm(
    const int* __restrict__ label,
    float* __restrict__ out)
{
    extern __shared__ __align__(128) char dyn[];

    const int tid = threadIdx.x;
    const int lane = tid & 31;
    const int wid = tid >> 5;
    const uint32_t sbase = smem_u32(dyn);
    const int p = blockIdx.x;
    const int G = gridDim.x;

    if (p >= NTILES) return;
    const int myTiles = (NTILES - 1 - p) / G + 1;
    const int FMAX = myTiles * NCHUNKS;

    // warp grid 4(b) x 4(c): each warp computes 32 x 32
    const int warp_b = (wid & 3) * 32;
    const int warp_c = (wid >> 2) * 32;
    const int gid = lane >> 2;
    const int tig = lane & 3;

    // fp16 ldmatrix.x4 lane mapping: row-in-16 = lane&15, 16B k-chunk = lane>>4
    const int frow = lane & 15;
    const int fcq = lane >> 4;

    float acc[2][4][4];
    #pragma unroll
    for (int i = 0; i < 2; i++)
        #pragma unroll
        for (int j = 0; j < 4; j++)
            #pragma unroll
            for (int k = 0; k < 4; k++) acc[i][j][k] = 0.0f;

    // ---- flattened-chunk loader: f -> (tile, chunk); 4096 x 16B cp.async ----
    auto load_f = [&](int f) {
        const int t = p + (f >> 2) * G;
        const int k0 = (f & 3) * BK;
        const int bb = (t & (NBT - 1)) * BM;
        const int cb = (t >> 3) * BN;
        const uint32_t ab = sbase + (f % STAGES) * STAGE_BYTES;
        #pragma unroll
        for (int l = 0; l < 4; l++) {           // A: 2048 ops
            int op = tid + l * NTHREADS;
            int r = op >> 4, q = op & 15;       // q: 16B chunk = 8 fp16
            uint32_t sa = ab + r * 256 + ((q ^ (r & 7)) << 4);
            cp16(sa, g_xh + (bb + r) * DIM + k0 + q * 8, true);
        }
        #pragma unroll
        for (int l = 0; l < 4; l++) {           // B: 2048 ops
            int op = tid + l * NTHREADS;
            int r = op >> 4, q = op & 15;
            int cc = cb + r;
            uint32_t sa = ab + A_BYTES + r * 256 + ((q ^ (r & 7)) << 4);
            cp16(sa, g_wh + (size_t)cc * DIM + k0 + q * 8, cc < NCLS);
        }
    };

    // prologue: fill 2 stages (paid once per CTA lifetime)
    for (int f = 0; f < 2; f++) {
        if (f < FMAX) load_f(f);
        asm volatile("cp.async.commit_group;" ::: "memory");
    }

    // fp16 accumulators per chunk (128 k window), flushed to f32 each chunk
    uint32_t hacc[2][4][2];

    for (int f = 0; f < FMAX; f++) {
        asm volatile("cp.async.wait_group 1;" ::: "memory");
        __syncthreads();   // orders prior-iteration smem reads before stage overwrite

        if (f + 2 < FMAX) load_f(f + 2);
        asm volatile("cp.async.commit_group;" ::: "memory");

        const uint32_t a_stage = sbase + (f % STAGES) * STAGE_BYTES;
        const uint32_t b_stage = a_stage + A_BYTES;
        const int chunk = f & 3;

        #pragma unroll
        for (int i = 0; i < 2; i++)
            #pragma unroll
            for (int j = 0; j < 4; j++) { hacc[i][j][0] = 0u; hacc[i][j][1] = 0u; }

        #pragma unroll
        for (int s = 0; s < 8; s++) {           // 8 x k16 steps per 128-chunk
            const int q = 2 * s + fcq;          // 16B chunk within 256B row
            uint32_t bf[2][4];
            #pragma unroll
            for (int pp = 0; pp < 2; pp++) {
                int r = warp_c + pp * 16 + frow;
                uint32_t addr = b_stage + r * 256 + (((q ^ (r & 7)) & 15) << 4);
                ldsm_x4(bf[pp], addr);
            }
            #pragma unroll
            for (int mt = 0; mt < 2; mt++) {
                int r = warp_b + mt * 16 + frow;
                uint32_t addr = a_stage + r * 256 + (((q ^ (r & 7)) & 15) << 4);
                uint32_t af[4];
                ldsm_x4(af, addr);
                #pragma unroll
                for (int nt = 0; nt < 4; nt++)
                    mma_f16acc(hacc[mt][nt], af, bf[nt >> 1][nt & 1], bf[nt >> 1][(nt & 1) + 2]);
            }
        }

        // flush fp16 chunk accs (128 k window) into fp32 accumulators
        #pragma unroll
        for (int mt = 0; mt < 2; mt++)
            #pragma unroll
            for (int nt = 0; nt < 4; nt++) {
                float2 f0 = __half22float2(*(__half2*)&hacc[mt][nt][0]);
                float2 f1 = __half22float2(*(__half2*)&hacc[mt][nt][1]);
                acc[mt][nt][0] += f0.x;
                acc[mt][nt][1] += f0.y;
                acc[mt][nt][2] += f1.x;
                acc[mt][nt][3] += f1.y;
            }

        if (chunk == 3) {
            // ---- fused ArcFace epilogue for finished tile (regs+gmem only) ----
            const int t = p + (f >> 2) * G;
            const int bb = (t & (NBT - 1)) * BM;
            const int cb = (t >> 3) * BN;
            #pragma unroll
            for (int mt = 0; mt < 2; mt++) {
                int r = warp_b + mt * 16 + gid;
                int glb0 = bb + r;
                int glb1 = glb0 + 8;
                int lab0 = label[glb0];
                int lab1 = label[glb1];
                #pragma unroll
                for (int nt = 0; nt < 4; nt++) {
                    int c = cb + warp_c + nt * 8 + 2 * tig;
                    if (c >= NCLS) continue;  // c even, NCLS even -> c+1 valid when c < NCLS
                    float2 o0, o1;
                    o0.x = arcface(acc[mt][nt][0], lab0 == c);
                    o0.y = arcface(acc[mt][nt][1], lab0 == c + 1);
                    o1.x = arcface(acc[mt][nt][2], lab1 == c);
                    o1.y = arcface(acc[mt][nt][3], lab1 == c + 1);
                    *(float2*)(out + (size_t)glb0 * NCLS + c) = o0;
                    *(float2*)(out + (size_t)glb1 * NCLS + c) = o1;
                    acc[mt][nt][0] = 0.0f; acc[mt][nt][1] = 0.0f;
                    acc[mt][nt][2] = 0.0f; acc[mt][nt][3] = 0.0f;
                }
            }
        }
    }
}

extern "C" void kernel_launch(void* const* d_in, const int* in_sizes, int n_in,
                              void* d_out, int out_size) {
    const float* input  = (const float*)d_in[0];
    const int*   label  = (const int*)d_in[1];
    const float* weight = (const float*)d_in[2];
    float* out = (float*)d_out;

    cudaFuncSetAttribute(k_gemm, cudaFuncAttributeMaxDynamicSharedMemorySize, DYN_SMEM);

    int nsm = 148;
    cudaDeviceGetAttribute(&nsm, cudaDevAttrMultiProcessorCount, 0);

    // warp-per-row normalize: 256 threads = 8 rows per block
    k_rownorm<BATCH, 0><<<(BATCH + 7) / 8, 256>>>(input);
    k_rownorm<NCLS, 1><<<(NCLS + 7) / 8, 256>>>(weight);
    k_gemm<<<nsm, NTHREADS, DYN_SMEM>>>(label, out);
}

// round 15
// speedup vs baseline: 2.0263x; 1.0761x over previous
#include <cuda_runtime.h>
#include <cuda_fp16.h>
#include <cstdint>

// ---------------- problem constants ----------------
#define BATCH 1024
#define DIM   512
#define NCLS  100000

// ---------------- GEMM tiling ----------------
#define BM 128
#define BN 128
#define BK 128                           // k per chunk
#define KCH (DIM / BK)                   // 4 chunks per c-tile
#define NBT (BATCH / BM)                 // 8 b-tiles
#define NCT ((NCLS + BN - 1) / BN)       // 782 c-tiles
#define NSTG 3
#define A_RES_BYTES (BM * DIM * 2)       // 131072: A(bt) full-K resident
#define B_STAGE (BN * BK * 2)            // 32768
#define DYN_SMEM (A_RES_BYTES + NSTG * B_STAGE)  // 229376 <= 232448 cap
#define NTHREADS 512

// scratch (static device arrays — no allocation). Referenced ONLY in device code
// (host-side use of a __device__ symbol yields the shadow address — R7 bug).
__device__ __half g_xh[BATCH * DIM];            // normalized input, fp16-rn
__device__ __half g_wh[(size_t)NCLS * DIM];     // normalized weight, fp16-rn (102 MB)

// ---------------- helpers ----------------
__device__ __forceinline__ uint32_t smem_u32(const void* p) {
    uint32_t a;
    asm("{ .reg .u64 t; cvta.to.shared.u64 t, %1; cvt.u32.u64 %0, t; }" : "=r"(a) : "l"(p));
    return a;
}
__device__ __forceinline__ void cp16(uint32_t saddr, const void* g, bool valid) {
    int sz = valid ? 16 : 0;
    asm volatile("cp.async.cg.shared.global.L2::128B [%0], [%1], 16, %2;\n"
                 :: "r"(saddr), "l"(g), "r"(sz) : "memory");
}
__device__ __forceinline__ void ldsm_x4(uint32_t* r, uint32_t addr) {
    asm volatile("ldmatrix.sync.aligned.m8n8.x4.shared.b16 {%0,%1,%2,%3}, [%4];"
                 : "=r"(r[0]), "=r"(r[1]), "=r"(r[2]), "=r"(r[3]) : "r"(addr));
}
// m16n8k16 fp16 MMA, fp16 accumulate
__device__ __forceinline__ void mma_f16acc(uint32_t* d, const uint32_t* a, uint32_t b0, uint32_t b1) {
    asm volatile(
        "mma.sync.aligned.m16n8k16.row.col.f16.f16.f16.f16 "
        "{%0,%1}, {%2,%3,%4,%5}, {%6,%7}, {%0,%1};\n"
        : "+r"(d[0]), "+r"(d[1])
        : "r"(a[0]), "r"(a[1]), "r"(a[2]), "r"(a[3]), "r"(b0), "r"(b1));
}

// ---------------- fused row-normalize -> fp16 (warp per row, MLP=4) ----------------
// One kernel for BOTH tensors: rows [0,BATCH) from input -> g_xh,
// rows [BATCH, BATCH+NCLS) from weight -> g_wh.
__global__ void k_norm_all(const float* __restrict__ input,
                           const float* __restrict__ weight) {
    int gw = (blockIdx.x * blockDim.x + threadIdx.x) >> 5;
    int lane = threadIdx.x & 31;
    if (gw >= BATCH + NCLS) return;
    const bool isA = gw < BATCH;
    const int r = isA ? gw : gw - BATCH;
    const float* row = (isA ? input : weight) + (size_t)r * DIM;
    float4 v[4];
    #pragma unroll
    for (int i = 0; i < 4; i++) v[i] = *(const float4*)(row + lane * 4 + i * 128);
    float ss = 0.0f;
    #pragma unroll
    for (int i = 0; i < 4; i++)
        ss += v[i].x * v[i].x + v[i].y * v[i].y + v[i].z * v[i].z + v[i].w * v[i].w;
    #pragma unroll
    for (int o = 16; o; o >>= 1) ss += __shfl_xor_sync(0xffffffffu, ss, o);
    float inv = 1.0f / fmaxf(sqrtf(ss), 1e-12f);
    __half* drow = (isA ? g_xh : g_wh) + (size_t)r * DIM;   // device-side symbols
    #pragma unroll
    for (int i = 0; i < 4; i++) {
        __half2 h0 = __floats2half2_rn(v[i].x * inv, v[i].y * inv);
        __half2 h1 = __floats2half2_rn(v[i].z * inv, v[i].w * inv);
        uint2 pk;
        pk.x = *(uint32_t*)&h0;
        pk.y = *(uint32_t*)&h1;
        *(uint2*)(drow + lane * 4 + i * 128) = pk;
    }
}

// ---------------- ArcFace epilogue math ----------------
__device__ __forceinline__ float arcface(float cosv, bool tgt) {
    if (!tgt) return 30.0f * cosv;
    float s2 = fminf(fmaxf(1.0f - cosv * cosv, 0.0f), 1.0f);
    float sine = sqrtf(s2);
    float phi = cosv * 0.8775825618903728f - sine * 0.479425538604203f;
    phi = (cosv > -0.8775825618903728f) ? phi : (cosv - 7.191383079063045f);
    return 30.0f * phi;
}

// ---------------- persistent fp16 GEMM, A-resident in smem ----------------
// grid = (#SMs/8)*8 CTAs = NG groups x 8 b-tiles. CTA (bt = p&7, g = p>>3):
// loads A(bt) [128 x 512 fp16, 128 KB] into smem ONCE, then walks c-tiles
// ct = g, g+NG, ... streaming ONLY B chunks through a 3-stage cp.async
// pipeline (2048 cp.async/chunk — half of the A+B scheme). The 8 CTAs of a
// group walk the same ct sequence -> B served 8x from L2.
// Layouts: A resident rows 1024B (64 x 16B chunks): r*1024 + ((q^(r&7))<<4).
//          B stage rows 256B (16 x 16B chunks):     r*256  + ((q^(r&7))<<4).
// Both conflict-free for cp.async stores and ldmatrix reads.
__global__ void __launch_bounds__(NTHREADS, 1) k_gemm(
    const int* __restrict__ label,
    float* __restrict__ out)
{
    extern __shared__ __align__(128) char dyn[];

    const int tid = threadIdx.x;
    const int lane = tid & 31;
    const int wid = tid >> 5;
    const uint32_t a_res = smem_u32(dyn);
    const uint32_t b_base = a_res + A_RES_BYTES;

    const int G8 = (gridDim.x >> 3) << 3;
    const int p = blockIdx.x;
    if (p >= G8) return;
    const int bt = p & 7;
    const int lg = p >> 3;
    const int NG = G8 >> 3;
    if (lg >= NCT) return;
    const int nct = (NCT - 1 - lg) / NG + 1;
    const int FMAX = nct * KCH;

    // warp grid 4(b) x 4(c): each warp computes 32 x 32
    const int warp_b = (wid & 3) * 32;
    const int warp_c = (wid >> 2) * 32;
    const int gid = lane >> 2;
    const int tig = lane & 3;
    const int frow = lane & 15;     // ldmatrix: row-in-16
    const int fcq = lane >> 4;      // ldmatrix: 16B k-chunk select

    // labels for this CTA's fixed b-rows (hoisted: bt constant per CTA)
    int lab0[2], lab1[2];
    #pragma unroll
    for (int mt = 0; mt < 2; mt++) {
        int r = bt * BM + warp_b + mt * 16 + gid;
        lab0[mt] = label[r];
        lab1[mt] = label[r + 8];
    }

    // ---- load A(bt) resident: 8192 x 16B cp.async (16 per thread) ----
    #pragma unroll
    for (int i = 0; i < 16; i++) {
        int op = tid + i * NTHREADS;
        int r = op >> 6, q = op & 63;       // 64 chunks (16B) per 1024B row
        uint32_t sa = a_res + r * 1024 + ((q ^ (r & 7)) << 4);
        cp16(sa, g_xh + (bt * BM + r) * DIM + q * 8, true);
    }
    asm volatile("cp.async.commit_group;" ::: "memory");
    asm volatile("cp.async.wait_group 0;" ::: "memory");
    __syncthreads();

    float acc[2][4][4];
    #pragma unroll
    for (int i = 0; i < 2; i++)
        #pragma unroll
        for (int j = 0; j < 4; j++)
            #pragma unroll
            for (int k = 0; k < 4; k++) acc[i][j][k] = 0.0f;

    // ---- B chunk loader: f -> (ct, k-chunk); 2048 x 16B cp.async ----
    auto load_fB = [&](int f) {
        const int ct = lg + NG * (f >> 2);
        const int k0 = (f & 3) * BK;
        const int cb = ct * BN;
        const uint32_t ab = b_base + (f % NSTG) * B_STAGE;
        #pragma unroll
        for (int l = 0; l < 4; l++) {
            int op = tid + l * NTHREADS;
            int r = op >> 4, q = op & 15;   // 16 chunks (16B) per 256B row
            int cc = cb + r;
            uint32_t sa = ab + r * 256 + ((q ^ (r & 7)) << 4);
            cp16(sa, g_wh + (size_t)cc * DIM + k0 + q * 8, cc < NCLS);
        }
    };

    // prologue: 2 stages in flight
    load_fB(0);
    asm volatile("cp.async.commit_group;" ::: "memory");
    if (FMAX > 1) load_fB(1);
    asm volatile("cp.async.commit_group;" ::: "memory");

    uint32_t hacc[2][4][2];

    for (int f = 0; f < FMAX; f++) {
        asm volatile("cp.async.wait_group 1;" ::: "memory");
        __syncthreads();   // orders prior-iteration smem reads before stage overwrite

        if (f + 2 < FMAX) load_fB(f + 2);
        asm volatile("cp.async.commit_group;" ::: "memory");

        const uint32_t b_stage = b_base + (f % NSTG) * B_STAGE;
        const int chunk = f & 3;

        #pragma unroll
        for (int i = 0; i < 2; i++)
            #pragma unroll
            for (int j = 0; j < 4; j++) { hacc[i][j][0] = 0u; hacc[i][j][1] = 0u; }

        #pragma unroll
        for (int s = 0; s < 8; s++) {           // 8 x k16 steps per 128-chunk
            const int qb = 2 * s + fcq;              // B stage 16B-chunk [0,16)
            const int qa = chunk * 16 + 2 * s + fcq; // A resident 16B-chunk [0,64)
                                                     // (BK=128 halves = 16 x 16B — R13 bug was *8)
            uint32_t bf[2][4];
            #pragma unroll
            for (int pp = 0; pp < 2; pp++) {
                int r = warp_c + pp * 16 + frow;
                uint32_t addr = b_stage + r * 256 + ((qb ^ (r & 7)) << 4);
                ldsm_x4(bf[pp], addr);
            }
            #pragma unroll
            for (int mt = 0; mt < 2; mt++) {
                int r = warp_b + mt * 16 + frow;
                uint32_t addr = a_res + r * 1024 + ((qa ^ (r & 7)) << 4);
                uint32_t af[4];
                ldsm_x4(af, addr);
                #pragma unroll
                for (int nt = 0; nt < 4; nt++)
                    mma_f16acc(hacc[mt][nt], af, bf[nt >> 1][nt & 1], bf[nt >> 1][(nt & 1) + 2]);
            }
        }

        // flush fp16 chunk accs (128-k window) into fp32 accumulators
        #pragma unroll
        for (int mt = 0; mt < 2; mt++)
            #pragma unroll
            for (int nt = 0; nt < 4; nt++) {
                float2 f0 = __half22float2(*(__half2*)&hacc[mt][nt][0]);
                float2 f1 = __half22float2(*(__half2*)&hacc[mt][nt][1]);
                acc[mt][nt][0] += f0.x;
                acc[mt][nt][1] += f0.y;
                acc[mt][nt][2] += f1.x;
                acc[mt][nt][3] += f1.y;
            }

        if (chunk == 3) {
            // ---- fused ArcFace epilogue for finished c-tile (regs+gmem only) ----
            const int cb = (lg + NG * (f >> 2)) * BN;
            #pragma unroll
            for (int mt = 0; mt < 2; mt++) {
                int r = bt * BM + warp_b + mt * 16 + gid;
                #pragma unroll
                for (int nt = 0; nt < 4; nt++) {
                    int c = cb + warp_c + nt * 8 + 2 * tig;
                    if (c >= NCLS) continue;  // c even, NCLS even -> c+1 valid when c < NCLS
                    float2 o0, o1;
                    o0.x = arcface(acc[mt][nt][0], lab0[mt] == c);
                    o0.y = arcface(acc[mt][nt][1], lab0[mt] == c + 1);
                    o1.x = arcface(acc[mt][nt][2], lab1[mt] == c);
                    o1.y = arcface(acc[mt][nt][3], lab1[mt] == c + 1);
                    *(float2*)(out + (size_t)r * NCLS + c) = o0;
                    *(float2*)(out + (size_t)(r + 8) * NCLS + c) = o1;
                    acc[mt][nt][0] = 0.0f; acc[mt][nt][1] = 0.0f;
                    acc[mt][nt][2] = 0.0f; acc[mt][nt][3] = 0.0f;
                }
            }
        }
    }
}

extern "C" void kernel_launch(void* const* d_in, const int* in_sizes, int n_in,
                              void* d_out, int out_size) {
    const float* input  = (const float*)d_in[0];
    const int*   label  = (const int*)d_in[1];
    const float* weight = (const float*)d_in[2];
    float* out = (float*)d_out;

    cudaFuncSetAttribute(k_gemm, cudaFuncAttributeMaxDynamicSharedMemorySize, DYN_SMEM);

    int nsm = 148;
    cudaDeviceGetAttribute(&nsm, cudaDevAttrMultiProcessorCount, 0);
    int grid = (nsm / 8) * 8;   // multiple of 8 for the bt x group decomposition

    // single fused normalize pass (input + weight), warp per row
    int nwarps = BATCH + NCLS;
    k_norm_all<<<(nwarps * 32 + 255) / 256, 256>>>(input, weight);
    k_gemm<<<grid, NTHREADS, DYN_SMEM>>>(label, out);
}